// round 14
// baseline (speedup 1.0000x reference)
#include <cuda_runtime.h>
#include <cuda_fp16.h>
#include <math.h>
#include <stdint.h>

#define SEQ   8192
#define KDIM  512
#define DDIM  512

typedef __half fp16;

// ---------------- scratch (__device__ globals; no allocation allowed) -------
__device__ fp16  g_P  [(size_t)SEQ * SEQ];     // 128 MB exp(S) fp16
__device__ fp16  g_Qh [(size_t)SEQ * KDIM];
__device__ fp16  g_Kh [(size_t)SEQ * KDIM];
__device__ fp16  g_Vt [(size_t)KDIM * SEQ];    // V^T fp16
__device__ fp16  g_Wot[(size_t)DDIM * KDIM];   // Wo^T fp16
__device__ fp16  g_O1 [(size_t)SEQ * KDIM];
__device__ float g_rowsum[SEQ];

// ---------------------------------------------------------------------------
// fp16 GEMM, mma.sync + cp.async:  C = A * B^T   (A:[M,K], B:[N,K] fp16)
// fp32 accumulate. CTA 128x128, BK=64, 8 warps x (64x32), 2-stage smem,
// occupancy 2 (launch_bounds 256,2) + double-buffered ldmatrix fragments:
// ldsm for ks+1 issues before the MMAs of ks (regs ~124, at the 128 cap).
// ---------------------------------------------------------------------------
#define BM 128
#define BN 128
#define BK 64
#define SKEW 72                           // fp16/row: 64 data + 8 pad
#define TILE_B (128 * SKEW * 2)           // 18432 bytes
#define OFF_A 0
#define OFF_B TILE_B
#define STAGE_B (2 * TILE_B)              // 36864
#define NSTAGE 2
#define GEMM_SMEM (NSTAGE * STAGE_B)      // 73728 -> 2 CTAs/SM

#define EPI_PLAIN 0
#define EPI_EXP   1
#define EPI_SCALE 2

__device__ __forceinline__ uint32_t smem_u32(const void* p) {
    uint32_t a;
    asm("{ .reg .u64 t; cvta.to.shared.u64 t, %1; cvt.u32.u64 %0, t; }" : "=r"(a) : "l"(p));
    return a;
}
__device__ __forceinline__ void cpa16(uint32_t dst, const void* src) {
    asm volatile("cp.async.cg.shared.global [%0], [%1], 16;" :: "r"(dst), "l"(src));
}
__device__ __forceinline__ void ldsm4(uint32_t& r0, uint32_t& r1, uint32_t& r2,
                                      uint32_t& r3, uint32_t addr) {
    asm volatile("ldmatrix.sync.aligned.m8n8.x4.shared.b16 {%0,%1,%2,%3}, [%4];"
                 : "=r"(r0), "=r"(r1), "=r"(r2), "=r"(r3) : "r"(addr));
}
__device__ __forceinline__ void mma16816(float* d, const uint32_t* a, const uint32_t* b) {
    asm volatile(
        "mma.sync.aligned.m16n8k16.row.col.f32.f16.f16.f32 "
        "{%0,%1,%2,%3}, {%4,%5,%6,%7}, {%8,%9}, {%0,%1,%2,%3};"
        : "+f"(d[0]), "+f"(d[1]), "+f"(d[2]), "+f"(d[3])
        : "r"(a[0]), "r"(a[1]), "r"(a[2]), "r"(a[3]), "r"(b[0]), "r"(b[1]));
}

template <int EPI>
__global__ __launch_bounds__(256, 2) void gemm_fp16(
    const fp16* __restrict__ A, const fp16* __restrict__ B,
    float* __restrict__ Cf, fp16* __restrict__ Ch,
    float* __restrict__ rowsum, int K, int N, float alpha)
{
    extern __shared__ char sm[];
    const uint32_t smbase = smem_u32(sm);
    const int tid  = threadIdx.x;
    const int wid  = tid >> 5;
    const int lane = tid & 31;
    const int wm   = (wid >> 2) * 64;
    const int wn   = (wid & 3) * 32;

    const fp16* Ab = A + (size_t)blockIdx.y * BM * K;
    const fp16* Bb = B + (size_t)blockIdx.x * BN * K;

    float acc[4][4][4];
    #pragma unroll
    for (int i = 0; i < 4; i++)
        #pragma unroll
        for (int j = 0; j < 4; j++)
            #pragma unroll
            for (int r = 0; r < 4; r++) acc[i][j][r] = 0.0f;

    const int NC = K / BK;

    auto FILL = [&](int c, int s) {
        const uint32_t sb = smbase + (uint32_t)s * STAGE_B;
        #pragma unroll
        for (int i = 0; i < 4; i++) {
            const int idx = tid + i * 256;        // 0..1023
            const int row = idx >> 3;             // 0..127
            const int ch  = idx & 7;              // 16B chunk (8 per 128B row)
            const uint32_t d = (uint32_t)(row * SKEW + ch * 8) * 2;
            const size_t go = (size_t)row * K + (size_t)c * BK + ch * 8;
            cpa16(sb + OFF_A + d, Ab + go);
            cpa16(sb + OFF_B + d, Bb + go);
        }
    };

    const int rA   = lane & 15;
    const int colS = (lane >> 4) << 3;

    // double-buffered fragments
    uint32_t ah[2][4][4], bh[2][4][2];

    auto LOADFRAG = [&](int b, int ks, uint32_t base) {
        const int col = ks * 16 + colS;
        #pragma unroll
        for (int mi = 0; mi < 4; mi++) {
            const uint32_t ro = (uint32_t)((wm + mi * 16 + rA) * SKEW + col) * 2;
            ldsm4(ah[b][mi][0], ah[b][mi][1], ah[b][mi][2], ah[b][mi][3],
                  base + OFF_A + ro);
        }
        #pragma unroll
        for (int p = 0; p < 2; p++) {
            const uint32_t ro = (uint32_t)((wn + p * 16 + rA) * SKEW + col) * 2;
            uint32_t r0, r1, r2, r3;
            ldsm4(r0, r1, r2, r3, base + OFF_B + ro);
            bh[b][2 * p][0] = r0;     bh[b][2 * p][1] = r2;
            bh[b][2 * p + 1][0] = r1; bh[b][2 * p + 1][1] = r3;
        }
    };

    auto MMAS = [&](int b) {
        #pragma unroll
        for (int mi = 0; mi < 4; mi++)
            #pragma unroll
            for (int nj = 0; nj < 4; nj++)
                mma16816(acc[mi][nj], ah[b][mi], bh[b][nj]);
    };

    // ---- 2-stage pipeline; fill of c+2 issues after compute of c ----
    FILL(0, 0); asm volatile("cp.async.commit_group;");
    if (NC > 1) FILL(1, 1);
    asm volatile("cp.async.commit_group;");

    for (int c = 0; c < NC; c++) {
        asm volatile("cp.async.wait_group 1;");
        __syncthreads();                              // stage c ready
        const uint32_t base = smbase + (uint32_t)(c & 1) * STAGE_B;
        LOADFRAG(0, 0, base);
        #pragma unroll
        for (int ks = 0; ks < 4; ks++) {
            const int cur = ks & 1;
            if (ks < 3) LOADFRAG(cur ^ 1, ks + 1, base);
            MMAS(cur);
        }
        __syncthreads();                              // all warps done reading stage
        if (c + 2 < NC) FILL(c + 2, c & 1);
        asm volatile("cp.async.commit_group;");       // commit every iter (keeps numbering)
    }

    // ---- epilogue ----
    #pragma unroll
    for (int mi = 0; mi < 4; mi++) {
        const int r0 = blockIdx.y * BM + wm + mi * 16 + (lane >> 2);
        float rs0 = 0.0f, rs1 = 0.0f;
        float inv0 = 1.0f, inv1 = 1.0f;
        if (EPI == EPI_SCALE) {
            inv0 = 1.0f / rowsum[r0];
            inv1 = 1.0f / rowsum[r0 + 8];
        }
        #pragma unroll
        for (int nj = 0; nj < 4; nj++) {
            const int col = blockIdx.x * BN + wn + nj * 8 + 2 * (lane & 3);
            if (EPI == EPI_PLAIN) {
                *(float2*)(Cf + (size_t)r0 * N + col) =
                    make_float2(acc[mi][nj][0], acc[mi][nj][1]);
                *(float2*)(Cf + (size_t)(r0 + 8) * N + col) =
                    make_float2(acc[mi][nj][2], acc[mi][nj][3]);
            } else if (EPI == EPI_EXP) {
                float e0 = __expf(alpha * acc[mi][nj][0]);
                float e1 = __expf(alpha * acc[mi][nj][1]);
                float e2 = __expf(alpha * acc[mi][nj][2]);
                float e3 = __expf(alpha * acc[mi][nj][3]);
                *(__half2*)(Ch + (size_t)r0 * N + col) =
                    __floats2half2_rn(e0, e1);
                *(__half2*)(Ch + (size_t)(r0 + 8) * N + col) =
                    __floats2half2_rn(e2, e3);
                rs0 += e0 + e1;  rs1 += e2 + e3;
            } else { // EPI_SCALE
                *(__half2*)(Ch + (size_t)r0 * N + col) =
                    __floats2half2_rn(acc[mi][nj][0] * inv0, acc[mi][nj][1] * inv0);
                *(__half2*)(Ch + (size_t)(r0 + 8) * N + col) =
                    __floats2half2_rn(acc[mi][nj][2] * inv1, acc[mi][nj][3] * inv1);
            }
        }
        if (EPI == EPI_EXP) {
            rs0 += __shfl_xor_sync(0xffffffffu, rs0, 1);
            rs0 += __shfl_xor_sync(0xffffffffu, rs0, 2);
            rs1 += __shfl_xor_sync(0xffffffffu, rs1, 1);
            rs1 += __shfl_xor_sync(0xffffffffu, rs1, 2);
            if ((lane & 3) == 0) {
                atomicAdd(rowsum + r0, rs0);
                atomicAdd(rowsum + r0 + 8, rs1);
            }
        }
    }
}

// ---------------------------------------------------------------------------
// fp32 -> fp16 convert (vectorized: 4 elems/thread)
// ---------------------------------------------------------------------------
__global__ __launch_bounds__(256) void cvt_kernel(
    const float* __restrict__ in, fp16* __restrict__ out)
{
    const size_t i = (size_t)blockIdx.x * 256 + threadIdx.x;
    float4 v = ((const float4*)in)[i];
    ((__half2*)out)[2 * i]     = __floats2half2_rn(v.x, v.y);
    ((__half2*)out)[2 * i + 1] = __floats2half2_rn(v.z, v.w);
}

// ---------------------------------------------------------------------------
// Transpose + convert: in [R,C] fp32 -> out^T [C,R] fp16
// ---------------------------------------------------------------------------
__global__ __launch_bounds__(256) void transpose_cvt_kernel(
    const float* __restrict__ in, fp16* __restrict__ out, int R, int C)
{
    __shared__ float t[32][33];
    const int bx = blockIdx.x * 32;
    const int by = blockIdx.y * 32;
    #pragma unroll
    for (int j = threadIdx.y; j < 32; j += 8)
        t[j][threadIdx.x] = in[(size_t)(by + j) * C + bx + threadIdx.x];
    __syncthreads();
    #pragma unroll
    for (int j = threadIdx.y; j < 32; j += 8)
        out[(size_t)(bx + j) * R + by + threadIdx.x] =
            __float2half_rn(t[threadIdx.x][j]);
}

__global__ void zero_rowsum_kernel(float* __restrict__ rs)
{
    rs[blockIdx.x * 256 + threadIdx.x] = 0.0f;
}

// ---------------------------------------------------------------------------
extern "C" void kernel_launch(void* const* d_in, const int* in_sizes, int n_in,
                              void* d_out, int out_size)
{
    const float* Q  = (const float*)d_in[0];
    const float* Km = (const float*)d_in[1];
    const float* V  = (const float*)d_in[2];
    const float* Wo = (const float*)d_in[3];
    float* out = (float*)d_out;

    fp16 *P, *Qh, *Kh, *Vt, *Wot, *O1;
    float* rowsum;
    cudaGetSymbolAddress((void**)&P,   g_P);
    cudaGetSymbolAddress((void**)&Qh,  g_Qh);
    cudaGetSymbolAddress((void**)&Kh,  g_Kh);
    cudaGetSymbolAddress((void**)&Vt,  g_Vt);
    cudaGetSymbolAddress((void**)&Wot, g_Wot);
    cudaGetSymbolAddress((void**)&O1,  g_O1);
    cudaGetSymbolAddress((void**)&rowsum, g_rowsum);

    cudaFuncSetAttribute(gemm_fp16<EPI_PLAIN>,
                         cudaFuncAttributeMaxDynamicSharedMemorySize, GEMM_SMEM);
    cudaFuncSetAttribute(gemm_fp16<EPI_EXP>,
                         cudaFuncAttributeMaxDynamicSharedMemorySize, GEMM_SMEM);
    cudaFuncSetAttribute(gemm_fp16<EPI_SCALE>,
                         cudaFuncAttributeMaxDynamicSharedMemorySize, GEMM_SMEM);

    const float scale = 1.0f / sqrtf((float)KDIM);

    zero_rowsum_kernel<<<SEQ / 256, 256>>>(rowsum);
    cvt_kernel<<<(SEQ * KDIM / 4) / 256, 256>>>(Q, Qh);
    cvt_kernel<<<(SEQ * KDIM / 4) / 256, 256>>>(Km, Kh);
    transpose_cvt_kernel<<<dim3(KDIM / 32, SEQ / 32), dim3(32, 8)>>>(V, Vt, SEQ, KDIM);
    transpose_cvt_kernel<<<dim3(DDIM / 32, KDIM / 32), dim3(32, 8)>>>(Wo, Wot, KDIM, DDIM);

    // 1) P = exp(scale * Q K^T) (fp16), rowsum accumulated
    gemm_fp16<EPI_EXP><<<dim3(SEQ / BN, SEQ / BM), 256, GEMM_SMEM>>>(
        Qh, Kh, nullptr, P, rowsum, KDIM, SEQ, scale);
    // 2) O1 = (P V) / rowsum  (fp16)
    gemm_fp16<EPI_SCALE><<<dim3(KDIM / BN, SEQ / BM), 256, GEMM_SMEM>>>(
        P, Vt, nullptr, O1, rowsum, SEQ, KDIM, 1.0f);
    // 3) out = O1 Wo  (fp32 out)
    gemm_fp16<EPI_PLAIN><<<dim3(DDIM / BN, SEQ / BM), 256, GEMM_SMEM>>>(
        O1, Wot, out, nullptr, nullptr, KDIM, DDIM, 1.0f);
}

// round 15
// speedup vs baseline: 1.0032x; 1.0032x over previous
#include <cuda_runtime.h>
#include <cuda_fp16.h>
#include <math.h>
#include <stdint.h>

#define SEQ   8192
#define KDIM  512
#define DDIM  512

typedef __half fp16;

// ---------------- scratch (__device__ globals; no allocation allowed) -------
__device__ fp16  g_P  [(size_t)SEQ * SEQ];     // 128 MB exp(S) fp16
__device__ fp16  g_Qh [(size_t)SEQ * KDIM];
__device__ fp16  g_Kh [(size_t)SEQ * KDIM];
__device__ fp16  g_Vt [(size_t)KDIM * SEQ];    // V^T fp16
__device__ fp16  g_Wot[(size_t)DDIM * KDIM];   // Wo^T fp16
__device__ fp16  g_O1 [(size_t)SEQ * KDIM];
__device__ float g_rowsum[SEQ];

// ---------------------------------------------------------------------------
// fp16 GEMM, mma.sync + cp.async:  C = A * B^T   (A:[M,K], B:[N,K] fp16)
// fp32 accumulate. CTA 128x128, BK=64, 8 warps x (64x32), 2-stage smem,
// occupancy 2 (launch_bounds 256,2) + double-buffered ldmatrix fragments:
// ldsm for ks+1 issues before the MMAs of ks (regs ~124, at the 128 cap).
// ---------------------------------------------------------------------------
#define BM 128
#define BN 128
#define BK 64
#define SKEW 72                           // fp16/row: 64 data + 8 pad
#define TILE_B (128 * SKEW * 2)           // 18432 bytes
#define OFF_A 0
#define OFF_B TILE_B
#define STAGE_B (2 * TILE_B)              // 36864
#define NSTAGE 2
#define GEMM_SMEM (NSTAGE * STAGE_B)      // 73728 -> 2 CTAs/SM

#define EPI_PLAIN 0
#define EPI_EXP   1
#define EPI_SCALE 2

__device__ __forceinline__ uint32_t smem_u32(const void* p) {
    uint32_t a;
    asm("{ .reg .u64 t; cvta.to.shared.u64 t, %1; cvt.u32.u64 %0, t; }" : "=r"(a) : "l"(p));
    return a;
}
__device__ __forceinline__ void cpa16(uint32_t dst, const void* src) {
    asm volatile("cp.async.cg.shared.global [%0], [%1], 16;" :: "r"(dst), "l"(src));
}
__device__ __forceinline__ void ldsm4(uint32_t& r0, uint32_t& r1, uint32_t& r2,
                                      uint32_t& r3, uint32_t addr) {
    asm volatile("ldmatrix.sync.aligned.m8n8.x4.shared.b16 {%0,%1,%2,%3}, [%4];"
                 : "=r"(r0), "=r"(r1), "=r"(r2), "=r"(r3) : "r"(addr));
}
__device__ __forceinline__ void mma16816(float* d, const uint32_t* a, const uint32_t* b) {
    asm volatile(
        "mma.sync.aligned.m16n8k16.row.col.f32.f16.f16.f32 "
        "{%0,%1,%2,%3}, {%4,%5,%6,%7}, {%8,%9}, {%0,%1,%2,%3};"
        : "+f"(d[0]), "+f"(d[1]), "+f"(d[2]), "+f"(d[3])
        : "r"(a[0]), "r"(a[1]), "r"(a[2]), "r"(a[3]), "r"(b[0]), "r"(b[1]));
}

template <int EPI>
__global__ __launch_bounds__(256, 2) void gemm_fp16(
    const fp16* __restrict__ A, const fp16* __restrict__ B,
    float* __restrict__ Cf, fp16* __restrict__ Ch,
    float* __restrict__ rowsum, int K, int N, float alpha)
{
    extern __shared__ char sm[];
    const uint32_t smbase = smem_u32(sm);
    const int tid  = threadIdx.x;
    const int wid  = tid >> 5;
    const int lane = tid & 31;
    const int wm   = (wid >> 2) * 64;
    const int wn   = (wid & 3) * 32;

    const fp16* Ab = A + (size_t)blockIdx.y * BM * K;
    const fp16* Bb = B + (size_t)blockIdx.x * BN * K;

    float acc[4][4][4];
    #pragma unroll
    for (int i = 0; i < 4; i++)
        #pragma unroll
        for (int j = 0; j < 4; j++)
            #pragma unroll
            for (int r = 0; r < 4; r++) acc[i][j][r] = 0.0f;

    const int NC = K / BK;

    auto FILL = [&](int c, int s) {
        const uint32_t sb = smbase + (uint32_t)s * STAGE_B;
        #pragma unroll
        for (int i = 0; i < 4; i++) {
            const int idx = tid + i * 256;        // 0..1023
            const int row = idx >> 3;             // 0..127
            const int ch  = idx & 7;              // 16B chunk (8 per 128B row)
            const uint32_t d = (uint32_t)(row * SKEW + ch * 8) * 2;
            const size_t go = (size_t)row * K + (size_t)c * BK + ch * 8;
            cpa16(sb + OFF_A + d, Ab + go);
            cpa16(sb + OFF_B + d, Bb + go);
        }
    };

    const int rA   = lane & 15;
    const int colS = (lane >> 4) << 3;

    // double-buffered fragments
    uint32_t ah[2][4][4], bh[2][4][2];

    auto LOADFRAG = [&](int b, int ks, uint32_t base) {
        const int col = ks * 16 + colS;
        #pragma unroll
        for (int mi = 0; mi < 4; mi++) {
            const uint32_t ro = (uint32_t)((wm + mi * 16 + rA) * SKEW + col) * 2;
            ldsm4(ah[b][mi][0], ah[b][mi][1], ah[b][mi][2], ah[b][mi][3],
                  base + OFF_A + ro);
        }
        #pragma unroll
        for (int p = 0; p < 2; p++) {
            const uint32_t ro = (uint32_t)((wn + p * 16 + rA) * SKEW + col) * 2;
            uint32_t r0, r1, r2, r3;
            ldsm4(r0, r1, r2, r3, base + OFF_B + ro);
            bh[b][2 * p][0] = r0;     bh[b][2 * p][1] = r2;
            bh[b][2 * p + 1][0] = r1; bh[b][2 * p + 1][1] = r3;
        }
    };

    auto MMAS = [&](int b) {
        #pragma unroll
        for (int mi = 0; mi < 4; mi++)
            #pragma unroll
            for (int nj = 0; nj < 4; nj++)
                mma16816(acc[mi][nj], ah[b][mi], bh[b][nj]);
    };

    // ---- 2-stage pipeline; fill of c+2 issues after compute of c ----
    FILL(0, 0); asm volatile("cp.async.commit_group;");
    if (NC > 1) FILL(1, 1);
    asm volatile("cp.async.commit_group;");

    for (int c = 0; c < NC; c++) {
        asm volatile("cp.async.wait_group 1;");
        __syncthreads();                              // stage c ready
        const uint32_t base = smbase + (uint32_t)(c & 1) * STAGE_B;
        LOADFRAG(0, 0, base);
        #pragma unroll
        for (int ks = 0; ks < 4; ks++) {
            const int cur = ks & 1;
            if (ks < 3) LOADFRAG(cur ^ 1, ks + 1, base);
            MMAS(cur);
        }
        __syncthreads();                              // all warps done reading stage
        if (c + 2 < NC) FILL(c + 2, c & 1);
        asm volatile("cp.async.commit_group;");       // commit every iter (keeps numbering)
    }

    // ---- epilogue ----
    #pragma unroll
    for (int mi = 0; mi < 4; mi++) {
        const int r0 = blockIdx.y * BM + wm + mi * 16 + (lane >> 2);
        float rs0 = 0.0f, rs1 = 0.0f;
        float inv0 = 1.0f, inv1 = 1.0f;
        if (EPI == EPI_SCALE) {
            inv0 = 1.0f / rowsum[r0];
            inv1 = 1.0f / rowsum[r0 + 8];
        }
        #pragma unroll
        for (int nj = 0; nj < 4; nj++) {
            const int col = blockIdx.x * BN + wn + nj * 8 + 2 * (lane & 3);
            if (EPI == EPI_PLAIN) {
                *(float2*)(Cf + (size_t)r0 * N + col) =
                    make_float2(acc[mi][nj][0], acc[mi][nj][1]);
                *(float2*)(Cf + (size_t)(r0 + 8) * N + col) =
                    make_float2(acc[mi][nj][2], acc[mi][nj][3]);
            } else if (EPI == EPI_EXP) {
                float e0 = __expf(alpha * acc[mi][nj][0]);
                float e1 = __expf(alpha * acc[mi][nj][1]);
                float e2 = __expf(alpha * acc[mi][nj][2]);
                float e3 = __expf(alpha * acc[mi][nj][3]);
                *(__half2*)(Ch + (size_t)r0 * N + col) =
                    __floats2half2_rn(e0, e1);
                *(__half2*)(Ch + (size_t)(r0 + 8) * N + col) =
                    __floats2half2_rn(e2, e3);
                rs0 += e0 + e1;  rs1 += e2 + e3;
            } else { // EPI_SCALE
                *(__half2*)(Ch + (size_t)r0 * N + col) =
                    __floats2half2_rn(acc[mi][nj][0] * inv0, acc[mi][nj][1] * inv0);
                *(__half2*)(Ch + (size_t)(r0 + 8) * N + col) =
                    __floats2half2_rn(acc[mi][nj][2] * inv1, acc[mi][nj][3] * inv1);
            }
        }
        if (EPI == EPI_EXP) {
            rs0 += __shfl_xor_sync(0xffffffffu, rs0, 1);
            rs0 += __shfl_xor_sync(0xffffffffu, rs0, 2);
            rs1 += __shfl_xor_sync(0xffffffffu, rs1, 1);
            rs1 += __shfl_xor_sync(0xffffffffu, rs1, 2);
            if ((lane & 3) == 0) {
                atomicAdd(rowsum + r0, rs0);
                atomicAdd(rowsum + r0 + 8, rs1);
            }
        }
    }
}

// ---------------------------------------------------------------------------
// fp32 -> fp16 convert (vectorized: 4 elems/thread)
// ---------------------------------------------------------------------------
__global__ __launch_bounds__(256) void cvt_kernel(
    const float* __restrict__ in, fp16* __restrict__ out)
{
    const size_t i = (size_t)blockIdx.x * 256 + threadIdx.x;
    float4 v = ((const float4*)in)[i];
    ((__half2*)out)[2 * i]     = __floats2half2_rn(v.x, v.y);
    ((__half2*)out)[2 * i + 1] = __floats2half2_rn(v.z, v.w);
}

// ---------------------------------------------------------------------------
// Transpose + convert: in [R,C] fp32 -> out^T [C,R] fp16
// ---------------------------------------------------------------------------
__global__ __launch_bounds__(256) void transpose_cvt_kernel(
    const float* __restrict__ in, fp16* __restrict__ out, int R, int C)
{
    __shared__ float t[32][33];
    const int bx = blockIdx.x * 32;
    const int by = blockIdx.y * 32;
    #pragma unroll
    for (int j = threadIdx.y; j < 32; j += 8)
        t[j][threadIdx.x] = in[(size_t)(by + j) * C + bx + threadIdx.x];
    __syncthreads();
    #pragma unroll
    for (int j = threadIdx.y; j < 32; j += 8)
        out[(size_t)(bx + j) * R + by + threadIdx.x] =
            __float2half_rn(t[threadIdx.x][j]);
}

__global__ void zero_rowsum_kernel(float* __restrict__ rs)
{
    rs[blockIdx.x * 256 + threadIdx.x] = 0.0f;
}

// ---------------------------------------------------------------------------
extern "C" void kernel_launch(void* const* d_in, const int* in_sizes, int n_in,
                              void* d_out, int out_size)
{
    const float* Q  = (const float*)d_in[0];
    const float* Km = (const float*)d_in[1];
    const float* V  = (const float*)d_in[2];
    const float* Wo = (const float*)d_in[3];
    float* out = (float*)d_out;

    fp16 *P, *Qh, *Kh, *Vt, *Wot, *O1;
    float* rowsum;
    cudaGetSymbolAddress((void**)&P,   g_P);
    cudaGetSymbolAddress((void**)&Qh,  g_Qh);
    cudaGetSymbolAddress((void**)&Kh,  g_Kh);
    cudaGetSymbolAddress((void**)&Vt,  g_Vt);
    cudaGetSymbolAddress((void**)&Wot, g_Wot);
    cudaGetSymbolAddress((void**)&O1,  g_O1);
    cudaGetSymbolAddress((void**)&rowsum, g_rowsum);

    cudaFuncSetAttribute(gemm_fp16<EPI_PLAIN>,
                         cudaFuncAttributeMaxDynamicSharedMemorySize, GEMM_SMEM);
    cudaFuncSetAttribute(gemm_fp16<EPI_EXP>,
                         cudaFuncAttributeMaxDynamicSharedMemorySize, GEMM_SMEM);
    cudaFuncSetAttribute(gemm_fp16<EPI_SCALE>,
                         cudaFuncAttributeMaxDynamicSharedMemorySize, GEMM_SMEM);

    const float scale = 1.0f / sqrtf((float)KDIM);

    zero_rowsum_kernel<<<SEQ / 256, 256>>>(rowsum);
    cvt_kernel<<<(SEQ * KDIM / 4) / 256, 256>>>(Q, Qh);
    cvt_kernel<<<(SEQ * KDIM / 4) / 256, 256>>>(Km, Kh);
    transpose_cvt_kernel<<<dim3(KDIM / 32, SEQ / 32), dim3(32, 8)>>>(V, Vt, SEQ, KDIM);
    transpose_cvt_kernel<<<dim3(DDIM / 32, KDIM / 32), dim3(32, 8)>>>(Wo, Wot, KDIM, DDIM);

    // 1) P = exp(scale * Q K^T) (fp16), rowsum accumulated
    gemm_fp16<EPI_EXP><<<dim3(SEQ / BN, SEQ / BM), 256, GEMM_SMEM>>>(
        Qh, Kh, nullptr, P, rowsum, KDIM, SEQ, scale);
    // 2) O1 = (P V) / rowsum  (fp16)
    gemm_fp16<EPI_SCALE><<<dim3(KDIM / BN, SEQ / BM), 256, GEMM_SMEM>>>(
        P, Vt, nullptr, O1, rowsum, SEQ, KDIM, 1.0f);
    // 3) out = O1 Wo  (fp32 out)
    gemm_fp16<EPI_PLAIN><<<dim3(DDIM / BN, SEQ / BM), 256, GEMM_SMEM>>>(
        O1, Wot, out, nullptr, nullptr, KDIM, DDIM, 1.0f);
}